// round 9
// baseline (speedup 1.0000x reference)
#include <cuda_runtime.h>
#include <math.h>

#define D   512
#define NN  512
#define NQ  16
#define NCH 17
#define NECH 16

#define SCALE       22.62741699796952f
#define INV_SQRT_DH 0.04419417382415922f
#define PE_COEF     (-0.017988946039016837f)

typedef unsigned long long ull;

// ---------------- device scratch ----------------
__device__ float g_qh[NQ * D];
__device__ float g_part[NECH * NCH * D];
__device__ float g_G[NCH * D];
__device__ float g_A[NCH];
__device__ float g_C[NCH];
__device__ __align__(16) float g_peT[D * NN];

// ---------------- f32x2 helpers ----------------
__device__ __forceinline__ ull pk2(float a, float b) {
    ull r; asm("mov.b64 %0, {%1,%2};" : "=l"(r) : "f"(a), "f"(b)); return r;
}
__device__ __forceinline__ void upk2(ull v, float& a, float& b) {
    asm("mov.b64 {%0,%1}, %2;" : "=f"(a), "=f"(b) : "l"(v));
}
__device__ __forceinline__ void fma2(ull& d, ull a, ull b) {
    asm("fma.rn.f32x2 %0, %1, %2, %0;" : "+l"(d) : "l"(a), "l"(b));
}
__device__ __forceinline__ void add2(ull& d, ull a) {
    asm("add.rn.f32x2 %0, %0, %1;" : "+l"(d) : "l"(a));
}

// ---------------- kprep: PE table (blocks 0..1023) + q-LN@Wq (blocks 1024..1151) ----------------
__global__ void kprep(const float* __restrict__ query,
                      const float* __restrict__ lnqw,
                      const float* __restrict__ lnqb,
                      const float* __restrict__ Wq,
                      const float* __restrict__ bq) {
    if (blockIdx.x < 1024) {
        int idx = blockIdx.x * 256 + threadIdx.x;
        int d = idx >> 9;
        int n = idx & (NN - 1);
        int j = d >> 1;
        float freq = expf(PE_COEF * (float)(2 * j));
        float ang = (float)(NN - 1 - n) * freq;
        g_peT[idx] = (d & 1) ? cosf(ang) : sinf(ang);
        return;
    }
    __shared__ float qs[D];
    __shared__ float r1[8], r2[8];
    int bb = blockIdx.x - 1024;
    int q = bb >> 3, eb = (bb & 7) * 64;
    int tid = threadIdx.x, warp = tid >> 5, lane = tid & 31;

    float v0 = query[q * D + tid] * SCALE;
    float v1 = query[q * D + tid + 256] * SCALE;
    float s = v0 + v1, s2 = v0 * v0 + v1 * v1;
    #pragma unroll
    for (int o = 16; o; o >>= 1) {
        s  += __shfl_xor_sync(0xffffffffu, s,  o);
        s2 += __shfl_xor_sync(0xffffffffu, s2, o);
    }
    if (lane == 0) { r1[warp] = s; r2[warp] = s2; }
    __syncthreads();
    if (tid == 0) {
        float a = 0.f, b = 0.f;
        #pragma unroll
        for (int w = 0; w < 8; w++) { a += r1[w]; b += r2[w]; }
        r1[0] = a; r2[0] = b;
    }
    __syncthreads();
    float m = r1[0] * (1.f / D);
    float inv = rsqrtf(r2[0] * (1.f / D) - m * m + 1e-5f);
    qs[tid]       = (v0 - m) * inv * lnqw[tid] + lnqb[tid];
    qs[tid + 256] = (v1 - m) * inv * lnqw[tid + 256] + lnqb[tid + 256];
    __syncthreads();

    #pragma unroll
    for (int k = 0; k < 8; k++) {
        int e = eb + warp * 8 + k;
        const float* wrow = Wq + (size_t)e * D;
        float acc = 0.f;
        #pragma unroll 4
        for (int d = lane; d < D; d += 32) acc = fmaf(qs[d], wrow[d], acc);
        #pragma unroll
        for (int o = 16; o; o >>= 1) acc += __shfl_xor_sync(0xffffffffu, acc, o);
        if (lane == 0) g_qh[q * D + e] = acc + bq[e];
    }
}

// ---------------- k2p: split-E partials for Kq (16 ch) and u (ch 16) ----------------
__global__ void __launch_bounds__(128) k2p(const float* __restrict__ Wk,
                                           const float* __restrict__ Wv,
                                           const float* __restrict__ Wo) {
    __shared__ float cf[NCH * 32];
    int d = blockIdx.x * 128 + threadIdx.x;
    int ech = blockIdx.y;
    for (int i = threadIdx.x; i < NCH * 32; i += 128) {
        int ch = i >> 5, e = ech * 32 + (i & 31);
        cf[i] = (ch < NQ) ? g_qh[ch * D + e] : Wo[e];
    }
    __syncthreads();

    float acc[NCH];
    #pragma unroll
    for (int c = 0; c < NCH; c++) acc[c] = 0.f;
    #pragma unroll 4
    for (int ee = 0; ee < 32; ee++) {
        int e = ech * 32 + ee;
        float wk = Wk[(size_t)e * D + d];
        float wv = Wv[(size_t)e * D + d];
        #pragma unroll
        for (int c = 0; c < NQ; c++) acc[c] = fmaf(cf[c * 32 + ee], wk, acc[c]);
        acc[16] = fmaf(cf[16 * 32 + ee], wv, acc[16]);
    }
    #pragma unroll
    for (int c = 0; c < NCH; c++)
        g_part[((size_t)ech * NCH + c) * D + d] = acc[c];
}

// ---------------- k3r: reduce partials + fold LN weights -> G, A, C ----------------
__global__ void k3r(const float* __restrict__ lnw, const float* __restrict__ lnb,
                    const float* __restrict__ bk,  const float* __restrict__ bv,
                    const float* __restrict__ Wo) {
    __shared__ float rA[16], rB[16], rC[16];
    int ch = blockIdx.x;
    int d = threadIdx.x, warp = d >> 5, lane = d & 31;
    bool sc = ch < NQ;
    float chS = sc ? INV_SQRT_DH : 1.f;

    float src = 0.f;
    #pragma unroll
    for (int p = 0; p < NECH; p++)
        src += g_part[((size_t)p * NCH + ch) * D + d];

    float g = lnw[d] * src * chS;
    g_G[ch * D + d] = g;
    float aA = g;
    float aB = lnb[d] * src;
    float aC = sc ? g_qh[ch * D + d] * bk[d] : bv[d] * Wo[d];

    #pragma unroll
    for (int o = 16; o; o >>= 1) {
        aA += __shfl_xor_sync(0xffffffffu, aA, o);
        aB += __shfl_xor_sync(0xffffffffu, aB, o);
        aC += __shfl_xor_sync(0xffffffffu, aC, o);
    }
    if (lane == 0) { rA[warp] = aA; rB[warp] = aB; rC[warp] = aC; }
    __syncthreads();
    if (threadIdx.x == 0) {
        float A = 0.f, Bv = 0.f, C = 0.f;
        #pragma unroll
        for (int w = 0; w < 16; w++) { A += rA[w]; Bv += rB[w]; C += rC[w]; }
        g_A[ch] = A;
        g_C[ch] = (Bv + C) * chS;
    }
}

// ---------------- k4f: fused streaming + softmax + logits ----------------
// grid B, 256 threads, 2 tokens/thread (one f32x2 pair). Whole batch row in
// one block -> softmax fused, scores never touch DRAM.
__global__ void __launch_bounds__(256, 1) k4f(const float* __restrict__ latents,
                                              const float* __restrict__ qmask,
                                              const float* __restrict__ bo,
                                              float* __restrict__ logits_out,
                                              float* __restrict__ attn_out) {
    extern __shared__ ull Gs2[];   // NCH*D duplicated pairs (69632 B)
    __shared__ float redA[8], redB[8], redC[8];
    int tid = threadIdx.x;
    for (int i = tid; i < NCH * D; i += 256) {
        float g = g_G[i];
        Gs2[i] = pk2(g, g);
    }
    __syncthreads();

    int b = blockIdx.x;
    int n2 = tid * 2;
    const float* latB = latents + (size_t)b * D * NN;

    ull acc[NCH];
    #pragma unroll
    for (int c = 0; c < NCH; c++) acc[c] = 0ull;
    ull s0 = 0ull, s1 = 0ull;
    const ull SC2 = pk2(SCALE, SCALE);

    #pragma unroll 4
    for (int d = 0; d < D; d += 2) {
        ull lat0 = *(const ull*)(latB + (size_t)d * NN + n2);
        ull lat1 = *(const ull*)(latB + (size_t)(d + 1) * NN + n2);
        ull x0   = *(const ull*)(g_peT + (size_t)d * NN + n2);
        ull x1   = *(const ull*)(g_peT + (size_t)(d + 1) * NN + n2);
        fma2(x0, lat0, SC2);
        fma2(x1, lat1, SC2);
        add2(s0, x0); fma2(s1, x0, x0);
        add2(s0, x1); fma2(s1, x1, x1);
        #pragma unroll
        for (int c = 0; c < NCH; c++) {
            ulonglong2 g2 = *(const ulonglong2*)&Gs2[c * D + d];
            fma2(acc[c], x0, g2.x);
            fma2(acc[c], x1, g2.y);
        }
    }

    float sA, sB, qA, qB;
    upk2(s0, sA, sB);
    upk2(s1, qA, qB);
    float m0 = sA * (1.f / D), m1 = sB * (1.f / D);
    float i0 = rsqrtf(qA * (1.f / D) - m0 * m0 + 1e-5f);
    float i1 = rsqrtf(qB * (1.f / D) - m1 * m1 + 1e-5f);

    float sc0[NCH], sc1[NCH];
    #pragma unroll
    for (int c = 0; c < NCH; c++) {
        float t0, t1; upk2(acc[c], t0, t1);
        float A = g_A[c], Cc = g_C[c];
        sc0[c] = (t0 - m0 * A) * i0 + Cc;
        sc1[c] = (t1 - m1 * A) * i1 + Cc;
    }
    float v0 = sc0[16], v1 = sc1[16];

    int lane = tid & 31, warp = tid >> 5;
    float bo0 = bo[0];

    #pragma unroll 1
    for (int c = 0; c < NQ; c++) {
        // block max
        float mx = fmaxf(sc0[c], sc1[c]);
        #pragma unroll
        for (int o = 16; o; o >>= 1) mx = fmaxf(mx, __shfl_xor_sync(0xffffffffu, mx, o));
        if (lane == 0) redA[warp] = mx;
        __syncthreads();
        mx = redA[0];
        #pragma unroll
        for (int w = 1; w < 8; w++) mx = fmaxf(mx, redA[w]);

        float e0 = expf(sc0[c] - mx);
        float e1 = expf(sc1[c] - mx);
        float ps = e0 + e1;
        float pd = e0 * v0 + e1 * v1;
        #pragma unroll
        for (int o = 16; o; o >>= 1) {
            ps += __shfl_xor_sync(0xffffffffu, ps, o);
            pd += __shfl_xor_sync(0xffffffffu, pd, o);
        }
        if (lane == 0) { redB[warp] = ps; redC[warp] = pd; }
        __syncthreads();
        float S = redB[0], Dt = redC[0];
        #pragma unroll
        for (int w = 1; w < 8; w++) { S += redB[w]; Dt += redC[w]; }

        int row = b * NQ + c;
        float qm = qmask[row];
        if (qm != 0.f) {
            float inv = 1.f / S;
            if (attn_out) {
                float2 o2; o2.x = e0 * inv; o2.y = e1 * inv;
                *(float2*)(attn_out + (size_t)row * NN + n2) = o2;
            }
            if (tid == 0 && logits_out) logits_out[row] = Dt * inv + bo0;
        } else {
            if (attn_out) {
                float2 o2; o2.x = 1.f / NN; o2.y = 1.f / NN;
                *(float2*)(attn_out + (size_t)row * NN + n2) = o2;
            }
            if (tid == 0 && logits_out) logits_out[row] = bo0;
        }
        __syncthreads();   // protect redA/redB/redC reuse next channel
    }
}

// ---------------- launch ----------------
extern "C" void kernel_launch(void* const* d_in, const int* in_sizes, int n_in,
                              void* d_out, int out_size) {
    const float* latents = (const float*)d_in[0];
    const float* qmask   = (const float*)d_in[1];
    const float* query   = (const float*)d_in[2];
    const float* lnlw    = (const float*)d_in[3];
    const float* lnlb    = (const float*)d_in[4];
    const float* lnqw    = (const float*)d_in[5];
    const float* lnqb    = (const float*)d_in[6];
    const float* Wq      = (const float*)d_in[7];
    const float* bq      = (const float*)d_in[8];
    const float* Wk      = (const float*)d_in[9];
    const float* bk      = (const float*)d_in[10];
    const float* Wv      = (const float*)d_in[11];
    const float* bvv     = (const float*)d_in[12];
    const float* Wo      = (const float*)d_in[13];
    const float* bo      = (const float*)d_in[14];

    int B = in_sizes[0] / (D * NN);
    float* out = (float*)d_out;

    float* logits_out = nullptr;
    float* attn_out = nullptr;
    if (out_size == B * NQ * (NN + 1)) { logits_out = out; attn_out = out + (size_t)B * NQ; }
    else if (out_size == B * NQ * NN)  { attn_out = out; }
    else                               { logits_out = out; }

    kprep<<<1024 + 128, 256>>>(query, lnqw, lnqb, Wq, bq);
    k2p<<<dim3(4, NECH), 128>>>(Wk, Wv, Wo);
    k3r<<<NCH, 512>>>(lnlw, lnlb, bk, bvv, Wo);

    cudaFuncSetAttribute(k4f, cudaFuncAttributeMaxDynamicSharedMemorySize, NCH * D * 8);
    k4f<<<B, 256, NCH * D * 8>>>(latents, qmask, bo, logits_out, attn_out);
}

// round 10
// speedup vs baseline: 1.0029x; 1.0029x over previous
#include <cuda_runtime.h>
#include <math.h>

#define D   512
#define NN  512
#define NQ  16
#define NCH 17
#define NECH 16

#define SCALE       22.62741699796952f
#define INV_SQRT_DH 0.04419417382415922f
#define PE_COEF     (-0.017988946039016837f)

typedef unsigned long long ull;

// ---------------- device scratch ----------------
__device__ float g_qh[NQ * D];
__device__ float g_part[NECH * NCH * D];
__device__ float g_G[NCH * D];
__device__ float g_A[NCH];
__device__ float g_C[NCH];
__device__ __align__(16) float g_peT[D * NN];

// ---------------- f32x2 helpers ----------------
__device__ __forceinline__ ull pk2(float a, float b) {
    ull r; asm("mov.b64 %0, {%1,%2};" : "=l"(r) : "f"(a), "f"(b)); return r;
}
__device__ __forceinline__ void upk2(ull v, float& a, float& b) {
    asm("mov.b64 {%0,%1}, %2;" : "=f"(a), "=f"(b) : "l"(v));
}
__device__ __forceinline__ void fma2(ull& d, ull a, ull b) {
    asm("fma.rn.f32x2 %0, %1, %2, %0;" : "+l"(d) : "l"(a), "l"(b));
}
__device__ __forceinline__ void add2(ull& d, ull a) {
    asm("add.rn.f32x2 %0, %0, %1;" : "+l"(d) : "l"(a));
}

// ---------------- kprep: PE table (blocks 0..1023) + q-LN@Wq (blocks 1024..1151) ----------------
__global__ void kprep(const float* __restrict__ query,
                      const float* __restrict__ lnqw,
                      const float* __restrict__ lnqb,
                      const float* __restrict__ Wq,
                      const float* __restrict__ bq) {
    if (blockIdx.x < 1024) {
        int idx = blockIdx.x * 256 + threadIdx.x;
        int d = idx >> 9;
        int n = idx & (NN - 1);
        int j = d >> 1;
        float freq = expf(PE_COEF * (float)(2 * j));
        float ang = (float)(NN - 1 - n) * freq;
        g_peT[idx] = (d & 1) ? cosf(ang) : sinf(ang);
        return;
    }
    __shared__ float qs[D];
    __shared__ float r1[8], r2[8];
    int bb = blockIdx.x - 1024;
    int q = bb >> 3, eb = (bb & 7) * 64;
    int tid = threadIdx.x, warp = tid >> 5, lane = tid & 31;

    float v0 = query[q * D + tid] * SCALE;
    float v1 = query[q * D + tid + 256] * SCALE;
    float s = v0 + v1, s2 = v0 * v0 + v1 * v1;
    #pragma unroll
    for (int o = 16; o; o >>= 1) {
        s  += __shfl_xor_sync(0xffffffffu, s,  o);
        s2 += __shfl_xor_sync(0xffffffffu, s2, o);
    }
    if (lane == 0) { r1[warp] = s; r2[warp] = s2; }
    __syncthreads();
    if (tid == 0) {
        float a = 0.f, b = 0.f;
        #pragma unroll
        for (int w = 0; w < 8; w++) { a += r1[w]; b += r2[w]; }
        r1[0] = a; r2[0] = b;
    }
    __syncthreads();
    float m = r1[0] * (1.f / D);
    float inv = rsqrtf(r2[0] * (1.f / D) - m * m + 1e-5f);
    qs[tid]       = (v0 - m) * inv * lnqw[tid] + lnqb[tid];
    qs[tid + 256] = (v1 - m) * inv * lnqw[tid + 256] + lnqb[tid + 256];
    __syncthreads();

    #pragma unroll
    for (int k = 0; k < 8; k++) {
        int e = eb + warp * 8 + k;
        const float* wrow = Wq + (size_t)e * D;
        float acc = 0.f;
        #pragma unroll 4
        for (int d = lane; d < D; d += 32) acc = fmaf(qs[d], wrow[d], acc);
        #pragma unroll
        for (int o = 16; o; o >>= 1) acc += __shfl_xor_sync(0xffffffffu, acc, o);
        if (lane == 0) g_qh[q * D + e] = acc + bq[e];
    }
}

// ---------------- k2p: split-E partials for Kq (16 ch) and u (ch 16) ----------------
__global__ void __launch_bounds__(128) k2p(const float* __restrict__ Wk,
                                           const float* __restrict__ Wv,
                                           const float* __restrict__ Wo) {
    __shared__ float cf[NCH * 32];
    int d = blockIdx.x * 128 + threadIdx.x;
    int ech = blockIdx.y;
    for (int i = threadIdx.x; i < NCH * 32; i += 128) {
        int ch = i >> 5, e = ech * 32 + (i & 31);
        cf[i] = (ch < NQ) ? g_qh[ch * D + e] : Wo[e];
    }
    __syncthreads();

    float acc[NCH];
    #pragma unroll
    for (int c = 0; c < NCH; c++) acc[c] = 0.f;
    #pragma unroll 4
    for (int ee = 0; ee < 32; ee++) {
        int e = ech * 32 + ee;
        float wk = Wk[(size_t)e * D + d];
        float wv = Wv[(size_t)e * D + d];
        #pragma unroll
        for (int c = 0; c < NQ; c++) acc[c] = fmaf(cf[c * 32 + ee], wk, acc[c]);
        acc[16] = fmaf(cf[16 * 32 + ee], wv, acc[16]);
    }
    #pragma unroll
    for (int c = 0; c < NCH; c++)
        g_part[((size_t)ech * NCH + c) * D + d] = acc[c];
}

// ---------------- k3r: reduce partials + fold LN weights -> G, A, C ----------------
__global__ void k3r(const float* __restrict__ lnw, const float* __restrict__ lnb,
                    const float* __restrict__ bk,  const float* __restrict__ bv,
                    const float* __restrict__ Wo) {
    __shared__ float rA[16], rB[16], rC[16];
    int ch = blockIdx.x;
    int d = threadIdx.x, warp = d >> 5, lane = d & 31;
    bool sc = ch < NQ;
    float chS = sc ? INV_SQRT_DH : 1.f;

    float src = 0.f;
    #pragma unroll
    for (int p = 0; p < NECH; p++)
        src += g_part[((size_t)p * NCH + ch) * D + d];

    float g = lnw[d] * src * chS;
    g_G[ch * D + d] = g;
    float aA = g;
    float aB = lnb[d] * src;
    float aC = sc ? g_qh[ch * D + d] * bk[d] : bv[d] * Wo[d];

    #pragma unroll
    for (int o = 16; o; o >>= 1) {
        aA += __shfl_xor_sync(0xffffffffu, aA, o);
        aB += __shfl_xor_sync(0xffffffffu, aB, o);
        aC += __shfl_xor_sync(0xffffffffu, aC, o);
    }
    if (lane == 0) { rA[warp] = aA; rB[warp] = aB; rC[warp] = aC; }
    __syncthreads();
    if (threadIdx.x == 0) {
        float A = 0.f, Bv = 0.f, C = 0.f;
        #pragma unroll
        for (int w = 0; w < 16; w++) { A += rA[w]; Bv += rB[w]; C += rC[w]; }
        g_A[ch] = A;
        g_C[ch] = (Bv + C) * chS;
    }
}

// ---------------- k4f: fused streaming + softmax + logits ----------------
// grid B, 256 threads, 2 tokens/thread (one f32x2 pair). Whole batch row in
// one block -> softmax fused, scores never touch DRAM.
__global__ void __launch_bounds__(256, 1) k4f(const float* __restrict__ latents,
                                              const float* __restrict__ qmask,
                                              const float* __restrict__ bo,
                                              float* __restrict__ logits_out,
                                              float* __restrict__ attn_out) {
    extern __shared__ ull Gs2[];   // NCH*D duplicated pairs (69632 B)
    __shared__ float redA[8], redB[8], redC[8];
    int tid = threadIdx.x;
    for (int i = tid; i < NCH * D; i += 256) {
        float g = g_G[i];
        Gs2[i] = pk2(g, g);
    }
    __syncthreads();

    int b = blockIdx.x;
    int n2 = tid * 2;
    const float* latB = latents + (size_t)b * D * NN;

    ull acc[NCH];
    #pragma unroll
    for (int c = 0; c < NCH; c++) acc[c] = 0ull;
    ull s0 = 0ull, s1 = 0ull;
    const ull SC2 = pk2(SCALE, SCALE);

    #pragma unroll 4
    for (int d = 0; d < D; d += 2) {
        ull lat0 = *(const ull*)(latB + (size_t)d * NN + n2);
        ull lat1 = *(const ull*)(latB + (size_t)(d + 1) * NN + n2);
        ull x0   = *(const ull*)(g_peT + (size_t)d * NN + n2);
        ull x1   = *(const ull*)(g_peT + (size_t)(d + 1) * NN + n2);
        fma2(x0, lat0, SC2);
        fma2(x1, lat1, SC2);
        add2(s0, x0); fma2(s1, x0, x0);
        add2(s0, x1); fma2(s1, x1, x1);
        #pragma unroll
        for (int c = 0; c < NCH; c++) {
            ulonglong2 g2 = *(const ulonglong2*)&Gs2[c * D + d];
            fma2(acc[c], x0, g2.x);
            fma2(acc[c], x1, g2.y);
        }
    }

    float sA, sB, qA, qB;
    upk2(s0, sA, sB);
    upk2(s1, qA, qB);
    float m0 = sA * (1.f / D), m1 = sB * (1.f / D);
    float i0 = rsqrtf(qA * (1.f / D) - m0 * m0 + 1e-5f);
    float i1 = rsqrtf(qB * (1.f / D) - m1 * m1 + 1e-5f);

    float sc0[NCH], sc1[NCH];
    #pragma unroll
    for (int c = 0; c < NCH; c++) {
        float t0, t1; upk2(acc[c], t0, t1);
        float A = g_A[c], Cc = g_C[c];
        sc0[c] = (t0 - m0 * A) * i0 + Cc;
        sc1[c] = (t1 - m1 * A) * i1 + Cc;
    }
    float v0 = sc0[16], v1 = sc1[16];

    int lane = tid & 31, warp = tid >> 5;
    float bo0 = bo[0];

    #pragma unroll 1
    for (int c = 0; c < NQ; c++) {
        // block max
        float mx = fmaxf(sc0[c], sc1[c]);
        #pragma unroll
        for (int o = 16; o; o >>= 1) mx = fmaxf(mx, __shfl_xor_sync(0xffffffffu, mx, o));
        if (lane == 0) redA[warp] = mx;
        __syncthreads();
        mx = redA[0];
        #pragma unroll
        for (int w = 1; w < 8; w++) mx = fmaxf(mx, redA[w]);

        float e0 = expf(sc0[c] - mx);
        float e1 = expf(sc1[c] - mx);
        float ps = e0 + e1;
        float pd = e0 * v0 + e1 * v1;
        #pragma unroll
        for (int o = 16; o; o >>= 1) {
            ps += __shfl_xor_sync(0xffffffffu, ps, o);
            pd += __shfl_xor_sync(0xffffffffu, pd, o);
        }
        if (lane == 0) { redB[warp] = ps; redC[warp] = pd; }
        __syncthreads();
        float S = redB[0], Dt = redC[0];
        #pragma unroll
        for (int w = 1; w < 8; w++) { S += redB[w]; Dt += redC[w]; }

        int row = b * NQ + c;
        float qm = qmask[row];
        if (qm != 0.f) {
            float inv = 1.f / S;
            if (attn_out) {
                float2 o2; o2.x = e0 * inv; o2.y = e1 * inv;
                *(float2*)(attn_out + (size_t)row * NN + n2) = o2;
            }
            if (tid == 0 && logits_out) logits_out[row] = Dt * inv + bo0;
        } else {
            if (attn_out) {
                float2 o2; o2.x = 1.f / NN; o2.y = 1.f / NN;
                *(float2*)(attn_out + (size_t)row * NN + n2) = o2;
            }
            if (tid == 0 && logits_out) logits_out[row] = bo0;
        }
        __syncthreads();   // protect redA/redB/redC reuse next channel
    }
}

// ---------------- launch ----------------
extern "C" void kernel_launch(void* const* d_in, const int* in_sizes, int n_in,
                              void* d_out, int out_size) {
    const float* latents = (const float*)d_in[0];
    const float* qmask   = (const float*)d_in[1];
    const float* query   = (const float*)d_in[2];
    const float* lnlw    = (const float*)d_in[3];
    const float* lnlb    = (const float*)d_in[4];
    const float* lnqw    = (const float*)d_in[5];
    const float* lnqb    = (const float*)d_in[6];
    const float* Wq      = (const float*)d_in[7];
    const float* bq      = (const float*)d_in[8];
    const float* Wk      = (const float*)d_in[9];
    const float* bk      = (const float*)d_in[10];
    const float* Wv      = (const float*)d_in[11];
    const float* bvv     = (const float*)d_in[12];
    const float* Wo      = (const float*)d_in[13];
    const float* bo      = (const float*)d_in[14];

    int B = in_sizes[0] / (D * NN);
    float* out = (float*)d_out;

    float* logits_out = nullptr;
    float* attn_out = nullptr;
    if (out_size == B * NQ * (NN + 1)) { logits_out = out; attn_out = out + (size_t)B * NQ; }
    else if (out_size == B * NQ * NN)  { attn_out = out; }
    else                               { logits_out = out; }

    kprep<<<1024 + 128, 256>>>(query, lnqw, lnqb, Wq, bq);
    k2p<<<dim3(4, NECH), 128>>>(Wk, Wv, Wo);
    k3r<<<NCH, 512>>>(lnlw, lnlb, bk, bvv, Wo);

    cudaFuncSetAttribute(k4f, cudaFuncAttributeMaxDynamicSharedMemorySize, NCH * D * 8);
    k4f<<<B, 256, NCH * D * 8>>>(latents, qmask, bo, logits_out, attn_out);
}

// round 13
// speedup vs baseline: 1.0061x; 1.0032x over previous
#include <cuda_runtime.h>
#include <math.h>

#define D   512
#define NN  512
#define NQ  16
#define NCH 17
#define NECH 16

#define SCALE       22.62741699796952f
#define INV_SQRT_DH 0.04419417382415922f
#define PE_COEF     (-0.017988946039016837f)

typedef unsigned long long ull;

// ---------------- device scratch ----------------
__device__ float g_qh[NQ * D];
__device__ float g_part[NECH * NCH * D];
__device__ float g_G[NCH * D];
__device__ float g_A[NCH];
__device__ float g_C[NCH];
__device__ __align__(16) float g_peT[D * NN];

// ---------------- f32x2 helpers ----------------
__device__ __forceinline__ ull pk2(float a, float b) {
    ull r; asm("mov.b64 %0, {%1,%2};" : "=l"(r) : "f"(a), "f"(b)); return r;
}
__device__ __forceinline__ void upk2(ull v, float& a, float& b) {
    asm("mov.b64 {%0,%1}, %2;" : "=f"(a), "=f"(b) : "l"(v));
}
__device__ __forceinline__ void fma2(ull& d, ull a, ull b) {
    asm("fma.rn.f32x2 %0, %1, %2, %0;" : "+l"(d) : "l"(a), "l"(b));
}
__device__ __forceinline__ void add2(ull& d, ull a) {
    asm("add.rn.f32x2 %0, %0, %1;" : "+l"(d) : "l"(a));
}

// ---------------- kprep: PE table (blocks 0..1023) + q-LN@Wq (blocks 1024..1151) ----------------
__global__ void kprep(const float* __restrict__ query,
                      const float* __restrict__ lnqw,
                      const float* __restrict__ lnqb,
                      const float* __restrict__ Wq,
                      const float* __restrict__ bq) {
    if (blockIdx.x < 1024) {
        int idx = blockIdx.x * 256 + threadIdx.x;
        int d = idx >> 9;
        int n = idx & (NN - 1);
        int j = d >> 1;
        float freq = expf(PE_COEF * (float)(2 * j));
        float ang = (float)(NN - 1 - n) * freq;
        g_peT[idx] = (d & 1) ? cosf(ang) : sinf(ang);
        return;
    }
    __shared__ float qs[D];
    __shared__ float r1[8], r2[8];
    int bb = blockIdx.x - 1024;
    int q = bb >> 3, eb = (bb & 7) * 64;
    int tid = threadIdx.x, warp = tid >> 5, lane = tid & 31;

    float v0 = query[q * D + tid] * SCALE;
    float v1 = query[q * D + tid + 256] * SCALE;
    float s = v0 + v1, s2 = v0 * v0 + v1 * v1;
    #pragma unroll
    for (int o = 16; o; o >>= 1) {
        s  += __shfl_xor_sync(0xffffffffu, s,  o);
        s2 += __shfl_xor_sync(0xffffffffu, s2, o);
    }
    if (lane == 0) { r1[warp] = s; r2[warp] = s2; }
    __syncthreads();
    if (tid == 0) {
        float a = 0.f, b = 0.f;
        #pragma unroll
        for (int w = 0; w < 8; w++) { a += r1[w]; b += r2[w]; }
        r1[0] = a; r2[0] = b;
    }
    __syncthreads();
    float m = r1[0] * (1.f / D);
    float inv = rsqrtf(r2[0] * (1.f / D) - m * m + 1e-5f);
    qs[tid]       = (v0 - m) * inv * lnqw[tid] + lnqb[tid];
    qs[tid + 256] = (v1 - m) * inv * lnqw[tid + 256] + lnqb[tid + 256];
    __syncthreads();

    #pragma unroll
    for (int k = 0; k < 8; k++) {
        int e = eb + warp * 8 + k;
        const float* wrow = Wq + (size_t)e * D;
        float acc = 0.f;
        #pragma unroll 4
        for (int d = lane; d < D; d += 32) acc = fmaf(qs[d], wrow[d], acc);
        #pragma unroll
        for (int o = 16; o; o >>= 1) acc += __shfl_xor_sync(0xffffffffu, acc, o);
        if (lane == 0) g_qh[q * D + e] = acc + bq[e];
    }
}

// ---------------- k2p: split-E partials for Kq (16 ch) and u (ch 16) ----------------
__global__ void __launch_bounds__(128) k2p(const float* __restrict__ Wk,
                                           const float* __restrict__ Wv,
                                           const float* __restrict__ Wo) {
    __shared__ float cf[NCH * 32];
    int d = blockIdx.x * 128 + threadIdx.x;
    int ech = blockIdx.y;
    for (int i = threadIdx.x; i < NCH * 32; i += 128) {
        int ch = i >> 5, e = ech * 32 + (i & 31);
        cf[i] = (ch < NQ) ? g_qh[ch * D + e] : Wo[e];
    }
    __syncthreads();

    float acc[NCH];
    #pragma unroll
    for (int c = 0; c < NCH; c++) acc[c] = 0.f;
    #pragma unroll 4
    for (int ee = 0; ee < 32; ee++) {
        int e = ech * 32 + ee;
        float wk = Wk[(size_t)e * D + d];
        float wv = Wv[(size_t)e * D + d];
        #pragma unroll
        for (int c = 0; c < NQ; c++) acc[c] = fmaf(cf[c * 32 + ee], wk, acc[c]);
        acc[16] = fmaf(cf[16 * 32 + ee], wv, acc[16]);
    }
    #pragma unroll
    for (int c = 0; c < NCH; c++)
        g_part[((size_t)ech * NCH + c) * D + d] = acc[c];
}

// ---------------- k3r: reduce partials + fold LN weights -> G, A, C ----------------
__global__ void k3r(const float* __restrict__ lnw, const float* __restrict__ lnb,
                    const float* __restrict__ bk,  const float* __restrict__ bv,
                    const float* __restrict__ Wo) {
    __shared__ float rA[16], rB[16], rC[16];
    int ch = blockIdx.x;
    int d = threadIdx.x, warp = d >> 5, lane = d & 31;
    bool sc = ch < NQ;
    float chS = sc ? INV_SQRT_DH : 1.f;

    float src = 0.f;
    #pragma unroll
    for (int p = 0; p < NECH; p++)
        src += g_part[((size_t)p * NCH + ch) * D + d];

    float g = lnw[d] * src * chS;
    g_G[ch * D + d] = g;
    float aA = g;
    float aB = lnb[d] * src;
    float aC = sc ? g_qh[ch * D + d] * bk[d] : bv[d] * Wo[d];

    #pragma unroll
    for (int o = 16; o; o >>= 1) {
        aA += __shfl_xor_sync(0xffffffffu, aA, o);
        aB += __shfl_xor_sync(0xffffffffu, aB, o);
        aC += __shfl_xor_sync(0xffffffffu, aC, o);
    }
    if (lane == 0) { rA[warp] = aA; rB[warp] = aB; rC[warp] = aC; }
    __syncthreads();
    if (threadIdx.x == 0) {
        float A = 0.f, Bv = 0.f, C = 0.f;
        #pragma unroll
        for (int w = 0; w < 16; w++) { A += rA[w]; Bv += rB[w]; C += rC[w]; }
        g_A[ch] = A;
        g_C[ch] = (Bv + C) * chS;
    }
}

// ---------------- k4f: fused streaming + softmax + logits ----------------
// grid B, 256 threads, 2 tokens/thread (one f32x2 pair). Whole batch row in
// one block -> softmax fused, scores never touch DRAM.
__global__ void __launch_bounds__(256, 1) k4f(const float* __restrict__ latents,
                                              const float* __restrict__ qmask,
                                              const float* __restrict__ bo,
                                              float* __restrict__ logits_out,
                                              float* __restrict__ attn_out) {
    extern __shared__ ull Gs2[];   // NCH*D duplicated pairs (69632 B)
    __shared__ float redA[8], redB[8], redC[8];
    int tid = threadIdx.x;
    for (int i = tid; i < NCH * D; i += 256) {
        float g = g_G[i];
        Gs2[i] = pk2(g, g);
    }
    __syncthreads();

    int b = blockIdx.x;
    int n2 = tid * 2;
    const float* latB = latents + (size_t)b * D * NN;

    ull acc[NCH];
    #pragma unroll
    for (int c = 0; c < NCH; c++) acc[c] = 0ull;
    ull s0 = 0ull, s1 = 0ull;
    const ull SC2 = pk2(SCALE, SCALE);

    #pragma unroll 4
    for (int d = 0; d < D; d += 2) {
        ull lat0 = *(const ull*)(latB + (size_t)d * NN + n2);
        ull lat1 = *(const ull*)(latB + (size_t)(d + 1) * NN + n2);
        ull x0   = *(const ull*)(g_peT + (size_t)d * NN + n2);
        ull x1   = *(const ull*)(g_peT + (size_t)(d + 1) * NN + n2);
        fma2(x0, lat0, SC2);
        fma2(x1, lat1, SC2);
        add2(s0, x0); fma2(s1, x0, x0);
        add2(s0, x1); fma2(s1, x1, x1);
        #pragma unroll
        for (int c = 0; c < NCH; c++) {
            ulonglong2 g2 = *(const ulonglong2*)&Gs2[c * D + d];
            fma2(acc[c], x0, g2.x);
            fma2(acc[c], x1, g2.y);
        }
    }

    float sA, sB, qA, qB;
    upk2(s0, sA, sB);
    upk2(s1, qA, qB);
    float m0 = sA * (1.f / D), m1 = sB * (1.f / D);
    float i0 = rsqrtf(qA * (1.f / D) - m0 * m0 + 1e-5f);
    float i1 = rsqrtf(qB * (1.f / D) - m1 * m1 + 1e-5f);

    float sc0[NCH], sc1[NCH];
    #pragma unroll
    for (int c = 0; c < NCH; c++) {
        float t0, t1; upk2(acc[c], t0, t1);
        float A = g_A[c], Cc = g_C[c];
        sc0[c] = (t0 - m0 * A) * i0 + Cc;
        sc1[c] = (t1 - m1 * A) * i1 + Cc;
    }
    float v0 = sc0[16], v1 = sc1[16];

    int lane = tid & 31, warp = tid >> 5;
    float bo0 = bo[0];

    #pragma unroll 1
    for (int c = 0; c < NQ; c++) {
        // block max
        float mx = fmaxf(sc0[c], sc1[c]);
        #pragma unroll
        for (int o = 16; o; o >>= 1) mx = fmaxf(mx, __shfl_xor_sync(0xffffffffu, mx, o));
        if (lane == 0) redA[warp] = mx;
        __syncthreads();
        mx = redA[0];
        #pragma unroll
        for (int w = 1; w < 8; w++) mx = fmaxf(mx, redA[w]);

        float e0 = expf(sc0[c] - mx);
        float e1 = expf(sc1[c] - mx);
        float ps = e0 + e1;
        float pd = e0 * v0 + e1 * v1;
        #pragma unroll
        for (int o = 16; o; o >>= 1) {
            ps += __shfl_xor_sync(0xffffffffu, ps, o);
            pd += __shfl_xor_sync(0xffffffffu, pd, o);
        }
        if (lane == 0) { redB[warp] = ps; redC[warp] = pd; }
        __syncthreads();
        float S = redB[0], Dt = redC[0];
        #pragma unroll
        for (int w = 1; w < 8; w++) { S += redB[w]; Dt += redC[w]; }

        int row = b * NQ + c;
        float qm = qmask[row];
        if (qm != 0.f) {
            float inv = 1.f / S;
            if (attn_out) {
                float2 o2; o2.x = e0 * inv; o2.y = e1 * inv;
                *(float2*)(attn_out + (size_t)row * NN + n2) = o2;
            }
            if (tid == 0 && logits_out) logits_out[row] = Dt * inv + bo0;
        } else {
            if (attn_out) {
                float2 o2; o2.x = 1.f / NN; o2.y = 1.f / NN;
                *(float2*)(attn_out + (size_t)row * NN + n2) = o2;
            }
            if (tid == 0 && logits_out) logits_out[row] = bo0;
        }
        __syncthreads();   // protect redA/redB/redC reuse next channel
    }
}

// ---------------- launch ----------------
extern "C" void kernel_launch(void* const* d_in, const int* in_sizes, int n_in,
                              void* d_out, int out_size) {
    const float* latents = (const float*)d_in[0];
    const float* qmask   = (const float*)d_in[1];
    const float* query   = (const float*)d_in[2];
    const float* lnlw    = (const float*)d_in[3];
    const float* lnlb    = (const float*)d_in[4];
    const float* lnqw    = (const float*)d_in[5];
    const float* lnqb    = (const float*)d_in[6];
    const float* Wq      = (const float*)d_in[7];
    const float* bq      = (const float*)d_in[8];
    const float* Wk      = (const float*)d_in[9];
    const float* bk      = (const float*)d_in[10];
    const float* Wv      = (const float*)d_in[11];
    const float* bvv     = (const float*)d_in[12];
    const float* Wo      = (const float*)d_in[13];
    const float* bo      = (const float*)d_in[14];

    int B = in_sizes[0] / (D * NN);
    float* out = (float*)d_out;

    float* logits_out = nullptr;
    float* attn_out = nullptr;
    if (out_size == B * NQ * (NN + 1)) { logits_out = out; attn_out = out + (size_t)B * NQ; }
    else if (out_size == B * NQ * NN)  { attn_out = out; }
    else                               { logits_out = out; }

    kprep<<<1024 + 128, 256>>>(query, lnqw, lnqb, Wq, bq);
    k2p<<<dim3(4, NECH), 128>>>(Wk, Wv, Wo);
    k3r<<<NCH, 512>>>(lnlw, lnlb, bk, bvv, Wo);

    cudaFuncSetAttribute(k4f, cudaFuncAttributeMaxDynamicSharedMemorySize, NCH * D * 8);
    k4f<<<B, 256, NCH * D * 8>>>(latents, qmask, bo, logits_out, attn_out);
}

// round 17
// speedup vs baseline: 1.1044x; 1.0977x over previous
#include <cuda_runtime.h>
#include <math.h>

#define D   512
#define NN  512
#define NQ  16
#define NCH 17
#define NECH 16
#define BMAX 128
#define NP  19      // 17 channels + s0 + s1

#define SCALE       22.62741699796952f
#define INV_SQRT_DH 0.04419417382415922f
#define PE_COEF     (-0.017988946039016837f)

typedef unsigned long long ull;

// ---------------- device scratch ----------------
__device__ float g_qh[NQ * D];
__device__ float g_part[NECH * NCH * D];
__device__ float g_G[NCH * D];
__device__ float g_A[NCH];
__device__ float g_C[NCH];
__device__ __align__(16) float g_peT[D * NN];
__device__ __align__(16) float g_pacc[BMAX * NP * 2 * NN];   // [b][c(19)][half][n]

// ---------------- f32x2 helpers ----------------
__device__ __forceinline__ ull pk2(float a, float b) {
    ull r; asm("mov.b64 %0, {%1,%2};" : "=l"(r) : "f"(a), "f"(b)); return r;
}
__device__ __forceinline__ void upk2(ull v, float& a, float& b) {
    asm("mov.b64 {%0,%1}, %2;" : "=f"(a), "=f"(b) : "l"(v));
}
__device__ __forceinline__ void fma2(ull& d, ull a, ull b) {
    asm("fma.rn.f32x2 %0, %1, %2, %0;" : "+l"(d) : "l"(a), "l"(b));
}
__device__ __forceinline__ void add2(ull& d, ull a) {
    asm("add.rn.f32x2 %0, %0, %1;" : "+l"(d) : "l"(a));
}

// ---------------- kprep: PE table (blocks 0..1023) + q-LN@Wq (blocks 1024..1151) ----------------
__global__ void kprep(const float* __restrict__ query,
                      const float* __restrict__ lnqw,
                      const float* __restrict__ lnqb,
                      const float* __restrict__ Wq,
                      const float* __restrict__ bq) {
    if (blockIdx.x < 1024) {
        int idx = blockIdx.x * 256 + threadIdx.x;
        int d = idx >> 9;
        int n = idx & (NN - 1);
        int j = d >> 1;
        float freq = expf(PE_COEF * (float)(2 * j));
        float ang = (float)(NN - 1 - n) * freq;
        g_peT[idx] = (d & 1) ? cosf(ang) : sinf(ang);
        return;
    }
    __shared__ float qs[D];
    __shared__ float r1[8], r2[8];
    int bb = blockIdx.x - 1024;
    int q = bb >> 3, eb = (bb & 7) * 64;
    int tid = threadIdx.x, warp = tid >> 5, lane = tid & 31;

    float v0 = query[q * D + tid] * SCALE;
    float v1 = query[q * D + tid + 256] * SCALE;
    float s = v0 + v1, s2 = v0 * v0 + v1 * v1;
    #pragma unroll
    for (int o = 16; o; o >>= 1) {
        s  += __shfl_xor_sync(0xffffffffu, s,  o);
        s2 += __shfl_xor_sync(0xffffffffu, s2, o);
    }
    if (lane == 0) { r1[warp] = s; r2[warp] = s2; }
    __syncthreads();
    if (tid == 0) {
        float a = 0.f, b = 0.f;
        #pragma unroll
        for (int w = 0; w < 8; w++) { a += r1[w]; b += r2[w]; }
        r1[0] = a; r2[0] = b;
    }
    __syncthreads();
    float m = r1[0] * (1.f / D);
    float inv = rsqrtf(r2[0] * (1.f / D) - m * m + 1e-5f);
    qs[tid]       = (v0 - m) * inv * lnqw[tid] + lnqb[tid];
    qs[tid + 256] = (v1 - m) * inv * lnqw[tid + 256] + lnqb[tid + 256];
    __syncthreads();

    #pragma unroll
    for (int k = 0; k < 8; k++) {
        int e = eb + warp * 8 + k;
        const float* wrow = Wq + (size_t)e * D;
        float acc = 0.f;
        #pragma unroll 4
        for (int d = lane; d < D; d += 32) acc = fmaf(qs[d], wrow[d], acc);
        #pragma unroll
        for (int o = 16; o; o >>= 1) acc += __shfl_xor_sync(0xffffffffu, acc, o);
        if (lane == 0) g_qh[q * D + e] = acc + bq[e];
    }
}

// ---------------- k2p: split-E partials for Kq (16 ch) and u (ch 16) ----------------
__global__ void __launch_bounds__(128) k2p(const float* __restrict__ Wk,
                                           const float* __restrict__ Wv,
                                           const float* __restrict__ Wo) {
    __shared__ float cf[NCH * 32];
    int d = blockIdx.x * 128 + threadIdx.x;
    int ech = blockIdx.y;
    for (int i = threadIdx.x; i < NCH * 32; i += 128) {
        int ch = i >> 5, e = ech * 32 + (i & 31);
        cf[i] = (ch < NQ) ? g_qh[ch * D + e] : Wo[e];
    }
    __syncthreads();

    float acc[NCH];
    #pragma unroll
    for (int c = 0; c < NCH; c++) acc[c] = 0.f;
    #pragma unroll 4
    for (int ee = 0; ee < 32; ee++) {
        int e = ech * 32 + ee;
        float wk = Wk[(size_t)e * D + d];
        float wv = Wv[(size_t)e * D + d];
        #pragma unroll
        for (int c = 0; c < NQ; c++) acc[c] = fmaf(cf[c * 32 + ee], wk, acc[c]);
        acc[16] = fmaf(cf[16 * 32 + ee], wv, acc[16]);
    }
    #pragma unroll
    for (int c = 0; c < NCH; c++)
        g_part[((size_t)ech * NCH + c) * D + d] = acc[c];
}

// ---------------- k3r: reduce partials + fold LN weights -> G, A, C ----------------
__global__ void k3r(const float* __restrict__ lnw, const float* __restrict__ lnb,
                    const float* __restrict__ bk,  const float* __restrict__ bv,
                    const float* __restrict__ Wo) {
    __shared__ float rA[16], rB[16], rC[16];
    int ch = blockIdx.x;
    int d = threadIdx.x, warp = d >> 5, lane = d & 31;
    bool sc = ch < NQ;
    float chS = sc ? INV_SQRT_DH : 1.f;

    float src = 0.f;
    #pragma unroll
    for (int p = 0; p < NECH; p++)
        src += g_part[((size_t)p * NCH + ch) * D + d];

    float g = lnw[d] * src * chS;
    g_G[ch * D + d] = g;
    float aA = g;
    float aB = lnb[d] * src;
    float aC = sc ? g_qh[ch * D + d] * bk[d] : bv[d] * Wo[d];

    #pragma unroll
    for (int o = 16; o; o >>= 1) {
        aA += __shfl_xor_sync(0xffffffffu, aA, o);
        aB += __shfl_xor_sync(0xffffffffu, aB, o);
        aC += __shfl_xor_sync(0xffffffffu, aC, o);
    }
    if (lane == 0) { rA[warp] = aA; rB[warp] = aB; rC[warp] = aC; }
    __syncthreads();
    if (threadIdx.x == 0) {
        float A = 0.f, Bv = 0.f, C = 0.f;
        #pragma unroll
        for (int w = 0; w < 16; w++) { A += rA[w]; Bv += rB[w]; C += rC[w]; }
        g_A[ch] = A;
        g_C[ch] = (Bv + C) * chS;
    }
}

// ---------------- k4p: streaming partial pass over a d-half ----------------
// grid (2 halves, B), 256 threads, 2 tokens/thread. 2 blocks/SM -> 16 warps.
__global__ void __launch_bounds__(256, 2) k4p(const float* __restrict__ latents) {
    __shared__ ull Gs2[NCH * 256];   // 34816 B, this half's coefficients duplicated
    int h = blockIdx.x;
    int b = blockIdx.y;
    int d0 = h * 256;
    int tid = threadIdx.x;
    for (int i = tid; i < NCH * 256; i += 256) {
        int c = i >> 8, dd = i & 255;
        float g = g_G[c * D + d0 + dd];
        Gs2[i] = pk2(g, g);
    }
    __syncthreads();

    int n2 = tid * 2;
    const float* latB = latents + ((size_t)b * D + d0) * NN;
    const float* peB  = g_peT + (size_t)d0 * NN;

    ull acc[NCH];
    #pragma unroll
    for (int c = 0; c < NCH; c++) acc[c] = 0ull;
    ull s0 = 0ull, s1 = 0ull;
    const ull SC2 = pk2(SCALE, SCALE);

    #pragma unroll 4
    for (int d = 0; d < 256; d += 2) {
        ull lat0 = *(const ull*)(latB + (size_t)d * NN + n2);
        ull lat1 = *(const ull*)(latB + (size_t)(d + 1) * NN + n2);
        ull x0   = *(const ull*)(peB + (size_t)d * NN + n2);
        ull x1   = *(const ull*)(peB + (size_t)(d + 1) * NN + n2);
        fma2(x0, lat0, SC2);
        fma2(x1, lat1, SC2);
        add2(s0, x0); fma2(s1, x0, x0);
        add2(s0, x1); fma2(s1, x1, x1);
        #pragma unroll
        for (int c = 0; c < NCH; c++) {
            ulonglong2 g2 = *(const ulonglong2*)&Gs2[c * 256 + d];
            fma2(acc[c], x0, g2.x);
            fma2(acc[c], x1, g2.y);
        }
    }

    // write 19 partial planes (coalesced float2 per plane)
    float* base = g_pacc + (((size_t)b * NP) * 2 + h) * NN + n2;
    #pragma unroll
    for (int c = 0; c < NCH; c++) {
        float t0, t1; upk2(acc[c], t0, t1);
        float2 o2; o2.x = t0; o2.y = t1;
        *(float2*)(base + (size_t)c * 2 * NN) = o2;
    }
    {
        float t0, t1; upk2(s0, t0, t1);
        float2 o2; o2.x = t0; o2.y = t1;
        *(float2*)(base + (size_t)17 * 2 * NN) = o2;
        upk2(s1, t0, t1);
        o2.x = t0; o2.y = t1;
        *(float2*)(base + (size_t)18 * 2 * NN) = o2;
    }
}

// ---------------- k5f: combine halves + LN finish + softmax + logits ----------------
__global__ void __launch_bounds__(256) k5f(const float* __restrict__ qmask,
                                           const float* __restrict__ bo,
                                           float* __restrict__ logits_out,
                                           float* __restrict__ attn_out) {
    __shared__ float redA[8], redB[8], redC[8];
    int b = blockIdx.x;
    int tid = threadIdx.x;
    int n2 = tid * 2;
    int lane = tid & 31, warp = tid >> 5;

    const float* base = g_pacc + ((size_t)b * NP) * 2 * NN + n2;
    float a0[NP], a1[NP];
    #pragma unroll
    for (int c = 0; c < NP; c++) {
        float2 p0 = *(const float2*)(base + (size_t)c * 2 * NN);
        float2 p1 = *(const float2*)(base + (size_t)c * 2 * NN + NN);
        a0[c] = p0.x + p1.x;
        a1[c] = p0.y + p1.y;
    }

    float m0 = a0[17] * (1.f / D), m1 = a1[17] * (1.f / D);
    float i0 = rsqrtf(a0[18] * (1.f / D) - m0 * m0 + 1e-5f);
    float i1 = rsqrtf(a1[18] * (1.f / D) - m1 * m1 + 1e-5f);

    float sc0[NCH], sc1[NCH];
    #pragma unroll
    for (int c = 0; c < NCH; c++) {
        float A = g_A[c], Cc = g_C[c];
        sc0[c] = (a0[c] - m0 * A) * i0 + Cc;
        sc1[c] = (a1[c] - m1 * A) * i1 + Cc;
    }
    float v0 = sc0[16], v1 = sc1[16];
    float bo0 = bo[0];

    #pragma unroll 1
    for (int c = 0; c < NQ; c++) {
        float mx = fmaxf(sc0[c], sc1[c]);
        #pragma unroll
        for (int o = 16; o; o >>= 1) mx = fmaxf(mx, __shfl_xor_sync(0xffffffffu, mx, o));
        if (lane == 0) redA[warp] = mx;
        __syncthreads();
        mx = redA[0];
        #pragma unroll
        for (int w = 1; w < 8; w++) mx = fmaxf(mx, redA[w]);

        float e0 = expf(sc0[c] - mx);
        float e1 = expf(sc1[c] - mx);
        float ps = e0 + e1;
        float pd = e0 * v0 + e1 * v1;
        #pragma unroll
        for (int o = 16; o; o >>= 1) {
            ps += __shfl_xor_sync(0xffffffffu, ps, o);
            pd += __shfl_xor_sync(0xffffffffu, pd, o);
        }
        if (lane == 0) { redB[warp] = ps; redC[warp] = pd; }
        __syncthreads();
        float S = redB[0], Dt = redC[0];
        #pragma unroll
        for (int w = 1; w < 8; w++) { S += redB[w]; Dt += redC[w]; }

        int row = b * NQ + c;
        float qm = qmask[row];
        if (qm != 0.f) {
            float inv = 1.f / S;
            if (attn_out) {
                float2 o2; o2.x = e0 * inv; o2.y = e1 * inv;
                *(float2*)(attn_out + (size_t)row * NN + n2) = o2;
            }
            if (tid == 0 && logits_out) logits_out[row] = Dt * inv + bo0;
        } else {
            if (attn_out) {
                float2 o2; o2.x = 1.f / NN; o2.y = 1.f / NN;
                *(float2*)(attn_out + (size_t)row * NN + n2) = o2;
            }
            if (tid == 0 && logits_out) logits_out[row] = bo0;
        }
        __syncthreads();
    }
}

// ---------------- launch ----------------
extern "C" void kernel_launch(void* const* d_in, const int* in_sizes, int n_in,
                              void* d_out, int out_size) {
    const float* latents = (const float*)d_in[0];
    const float* qmask   = (const float*)d_in[1];
    const float* query   = (const float*)d_in[2];
    const float* lnlw    = (const float*)d_in[3];
    const float* lnlb    = (const float*)d_in[4];
    const float* lnqw    = (const float*)d_in[5];
    const float* lnqb    = (const float*)d_in[6];
    const float* Wq      = (const float*)d_in[7];
    const float* bq      = (const float*)d_in[8];
    const float* Wk      = (const float*)d_in[9];
    const float* bk      = (const float*)d_in[10];
    const float* Wv      = (const float*)d_in[11];
    const float* bvv     = (const float*)d_in[12];
    const float* Wo      = (const float*)d_in[13];
    const float* bo      = (const float*)d_in[14];

    int B = in_sizes[0] / (D * NN);
    float* out = (float*)d_out;

    float* logits_out = nullptr;
    float* attn_out = nullptr;
    if (out_size == B * NQ * (NN + 1)) { logits_out = out; attn_out = out + (size_t)B * NQ; }
    else if (out_size == B * NQ * NN)  { attn_out = out; }
    else                               { logits_out = out; }

    kprep<<<1024 + 128, 256>>>(query, lnqw, lnqb, Wq, bq);
    k2p<<<dim3(4, NECH), 128>>>(Wk, Wv, Wo);
    k3r<<<NCH, 512>>>(lnlw, lnlb, bk, bvv, Wo);
    k4p<<<dim3(2, B), 256>>>(latents);
    k5f<<<B, 256>>>(qmask, bo, logits_out, attn_out);
}